// round 1
// baseline (speedup 1.0000x reference)
#include <cuda_runtime.h>
#include <math.h>

#define NIMG   32
#define HW     1024
#define NB     128
#define STRIPS_PER_IMG NB
#define NCTA   (NIMG * STRIPS_PER_IMG)
#define NBANDS 8
#define NVALS_PER_BAND (128.0 * 128.0 * 8.0)

__device__ __constant__ int BAND_OF[64] = {
    0,0,0,0,1,1,3,3,
    0,0,0,1,2,3,3,5,
    0,1,1,2,3,3,5,5,
    1,1,2,3,3,5,5,6,
    1,2,2,4,4,5,6,6,
    2,2,4,4,5,6,6,7,
    2,4,4,5,6,7,7,7,
    4,4,6,6,7,7,7,7
};

__device__ float g_part[NCTA * 16];

__global__ void __launch_bounds__(128)
dct_stats_kernel(const float* __restrict__ img, const float* __restrict__ dctm)
{
    __shared__ float Ds[32];
    int tid = threadIdx.x;
    if (tid < 32) {
        int l = tid >> 2, j = tid & 3;
        Ds[tid] = dctm[l * 8 + j];
    }
    __syncthreads();

    float Dr[8][4];
#pragma unroll
    for (int l = 0; l < 8; l++)
#pragma unroll
        for (int j = 0; j < 4; j++)
            Dr[l][j] = Ds[l * 4 + j];

    int g  = blockIdx.x;
    int b  = g >> 7;
    int by = g & 127;
    int bx = tid;

    const float* base = img + (size_t)b * 3u * HW * HW + (size_t)(by * 8) * HW + bx * 8;

    const float wr = 0.299f * 255.0f;
    const float wg = 0.587f * 255.0f;
    const float wb = 0.114f * 255.0f;

    float T[8][8];

#pragma unroll
    for (int i = 0; i < 8; i++) {
        const float* p = base + i * HW;
        float4 r0 = *(const float4*)(p);
        float4 r1 = *(const float4*)(p + 4);
        float4 g0 = *(const float4*)(p + HW * HW);
        float4 g1 = *(const float4*)(p + HW * HW + 4);
        float4 b0 = *(const float4*)(p + 2 * HW * HW);
        float4 b1 = *(const float4*)(p + 2 * HW * HW + 4);

        float x[8];
        x[0] = wr * r0.x + wg * g0.x + wb * b0.x;
        x[1] = wr * r0.y + wg * g0.y + wb * b0.y;
        x[2] = wr * r0.z + wg * g0.z + wb * b0.z;
        x[3] = wr * r0.w + wg * g0.w + wb * b0.w;
        x[4] = wr * r1.x + wg * g1.x + wb * b1.x;
        x[5] = wr * r1.y + wg * g1.y + wb * b1.y;
        x[6] = wr * r1.z + wg * g1.z + wb * b1.z;
        x[7] = wr * r1.w + wg * g1.w + wb * b1.w;

        float s[4], d[4];
#pragma unroll
        for (int j = 0; j < 4; j++) { s[j] = x[j] + x[7 - j]; d[j] = x[j] - x[7 - j]; }

#pragma unroll
        for (int l = 0; l < 8; l++) {
            float acc;
            if (l & 1)
                acc = d[0]*Dr[l][0] + d[1]*Dr[l][1] + d[2]*Dr[l][2] + d[3]*Dr[l][3];
            else
                acc = s[0]*Dr[l][0] + s[1]*Dr[l][1] + s[2]*Dr[l][2] + s[3]*Dr[l][3];
            T[i][l] = acc;
        }
    }

    float bs[8] = {0,0,0,0,0,0,0,0};
    float bq[8] = {0,0,0,0,0,0,0,0};

#pragma unroll
    for (int l = 0; l < 8; l++) {
        float s[4], d[4];
#pragma unroll
        for (int i = 0; i < 4; i++) {
            s[i] = T[i][l] + T[7 - i][l];
            d[i] = T[i][l] - T[7 - i][l];
        }
#pragma unroll
        for (int k = 0; k < 8; k++) {
            float y;
            if (k & 1)
                y = d[0]*Dr[k][0] + d[1]*Dr[k][1] + d[2]*Dr[k][2] + d[3]*Dr[k][3];
            else
                y = s[0]*Dr[k][0] + s[1]*Dr[k][1] + s[2]*Dr[k][2] + s[3]*Dr[k][3];
            float a = fabsf(y);
            int band = BAND_OF[k * 8 + l];
            bs[band] += a;
            bq[band] = fmaf(a, a, bq[band]);
        }
    }

#pragma unroll
    for (int m = 0; m < 8; m++) {
#pragma unroll
        for (int off = 16; off > 0; off >>= 1) {
            bs[m] += __shfl_down_sync(0xFFFFFFFFu, bs[m], off);
            bq[m] += __shfl_down_sync(0xFFFFFFFFu, bq[m], off);
        }
    }

    __shared__ float red[4][16];
    int wid = tid >> 5, lane = tid & 31;
    if (lane == 0) {
#pragma unroll
        for (int m = 0; m < 8; m++) {
            red[wid][m]     = bs[m];
            red[wid][8 + m] = bq[m];
        }
    }
    __syncthreads();
    if (tid < 16) {
        float v = red[0][tid] + red[1][tid] + red[2][tid] + red[3][tid];
        g_part[g * 16 + tid] = v;
    }
}

__global__ void __launch_bounds__(256)
finalize_kernel(const float* __restrict__ W, const float* __restrict__ bias,
                float* __restrict__ out)
{
    __shared__ float raw[16];
    int b   = blockIdx.x;
    int tid = threadIdx.x;

    if (tid < 8) {
        // per-band: reduce both sum (slot tid) and sumsq (slot tid+8) in double
        double sum = 0.0, sq = 0.0;
        const float* p = g_part + (size_t)(b * STRIPS_PER_IMG) * 16;
        for (int c = 0; c < STRIPS_PER_IMG; c++) {
            sum += (double)p[c * 16 + tid];
            sq  += (double)p[c * 16 + tid + 8];
        }
        double mean = sum / NVALS_PER_BAND;
        double var  = (sq - NVALS_PER_BAND * mean * mean) / (NVALS_PER_BAND - 1.0);
        if (var < 0.0) var = 0.0;
        raw[tid]     = (float)mean;
        raw[tid + 8] = (float)sqrt(var);
    }
    __syncthreads();

    for (int f = tid; f < 512; f += 256) {
        float acc = bias[f];
#pragma unroll
        for (int j = 0; j < 16; j++)
            acc = fmaf(raw[j], W[f * 16 + j], acc);
        out[b * 512 + f] = acc;
    }
}

extern "C" void kernel_launch(void* const* d_in, const int* in_sizes, int n_in,
                              void* d_out, int out_size)
{
    const float* img  = (const float*)d_in[0];
    const float* dctm = (const float*)d_in[1];
    const float* W    = (const float*)d_in[3];
    const float* bias = (const float*)d_in[4];
    float* out = (float*)d_out;

    dct_stats_kernel<<<NCTA, 128>>>(img, dctm);
    finalize_kernel<<<NIMG, 256>>>(W, bias, out);
}

// round 3
// speedup vs baseline: 1.6315x; 1.6315x over previous
#include <cuda_runtime.h>
#include <math.h>

#define NIMG   32
#define HW     1024
#define NB     128
#define NCTA   (NIMG * NB)
#define NVALS  131072.0   // 128*128*8 values per band per image

// Band id per DCT coefficient flat index (k*8+l), from the JPEG zigzag of
// the reference's _zigzag_flat(8). Fully-unrolled constant indexing =>
// folded to immediates at compile time.
__device__ constexpr int BAND_OF[64] = {
    0,0,0,0,1,1,3,3,
    0,0,0,1,2,3,3,5,
    0,1,1,2,3,3,5,5,
    1,1,2,3,3,5,5,6,
    1,2,2,4,4,5,6,6,
    2,2,4,4,5,6,6,7,
    2,4,4,5,6,7,7,7,
    4,4,6,6,7,7,7,7
};

__device__ float g_part[NCTA * 16];

// 8-point DCT-II with hardcoded immediates (matches _dct_matrix(8) in f32).
// Even/odd butterfly: ~34 FMA-class ops, FFMA-imm forms (rt_SMSP=1).
__device__ __forceinline__ void dct8(const float x[8], float o[8])
{
    float s0 = x[0] + x[7], s1 = x[1] + x[6], s2 = x[2] + x[5], s3 = x[3] + x[4];
    float d0 = x[0] - x[7], d1 = x[1] - x[6], d2 = x[2] - x[5], d3 = x[3] - x[4];
    float f0 = s0 + s3, f1 = s1 + s2;
    float e0 = s0 - s3, e1 = s1 - s2;

    o[0] = 0.35355339f * (f0 + f1);
    o[4] = 0.35355339f * (f0 - f1);
    o[2] = fmaf(0.46193977f, e0,  0.19134172f * e1);
    o[6] = fmaf(0.19134172f, e0, -0.46193977f * e1);

    o[1] = fmaf(0.49039264f, d0, fmaf( 0.41573481f, d1, fmaf( 0.27778512f, d2,  0.09754516f * d3)));
    o[3] = fmaf(0.41573481f, d0, fmaf(-0.09754516f, d1, fmaf(-0.49039264f, d2, -0.27778512f * d3)));
    o[5] = fmaf(0.27778512f, d0, fmaf(-0.49039264f, d1, fmaf( 0.09754516f, d2,  0.41573481f * d3)));
    o[7] = fmaf(0.09754516f, d0, fmaf(-0.27778512f, d1, fmaf( 0.41573481f, d2, -0.49039264f * d3)));
}

__global__ void __launch_bounds__(128)
dct_stats_kernel(const float* __restrict__ img)
{
    int g   = blockIdx.x;          // 4096 CTAs = 32 images * 128 strips
    int b   = g >> 7;              // image
    int by  = g & 127;             // 8-row strip
    int tid = threadIdx.x;         // block-column 0..127

    const float* base = img + (size_t)b * 3u * HW * HW + (size_t)(by * 8) * HW + tid * 8;

    // luma weights with x255 folded in (lum.max() <= 1 provably holds)
    const float wr = 0.299f * 255.0f;
    const float wg = 0.587f * 255.0f;
    const float wb = 0.114f * 255.0f;

    float T[8][8];   // stage-1 output: T[i][l]

#pragma unroll
    for (int i = 0; i < 8; i++) {
        const float* p = base + i * HW;
        float4 r0 = *(const float4*)(p);
        float4 r1 = *(const float4*)(p + 4);
        float4 g0 = *(const float4*)(p + HW * HW);
        float4 g1 = *(const float4*)(p + HW * HW + 4);
        float4 c0 = *(const float4*)(p + 2 * HW * HW);
        float4 c1 = *(const float4*)(p + 2 * HW * HW + 4);

        float x[8];
        x[0] = fmaf(wr, r0.x, fmaf(wg, g0.x, wb * c0.x));
        x[1] = fmaf(wr, r0.y, fmaf(wg, g0.y, wb * c0.y));
        x[2] = fmaf(wr, r0.z, fmaf(wg, g0.z, wb * c0.z));
        x[3] = fmaf(wr, r0.w, fmaf(wg, g0.w, wb * c0.w));
        x[4] = fmaf(wr, r1.x, fmaf(wg, g1.x, wb * c1.x));
        x[5] = fmaf(wr, r1.y, fmaf(wg, g1.y, wb * c1.y));
        x[6] = fmaf(wr, r1.z, fmaf(wg, g1.z, wb * c1.z));
        x[7] = fmaf(wr, r1.w, fmaf(wg, g1.w, wb * c1.w));

        float u[8];
        dct8(x, u);
#pragma unroll
        for (int l = 0; l < 8; l++) T[i][l] = u[l];
    }

    float bs[8] = {0,0,0,0,0,0,0,0};
    float bq[8] = {0,0,0,0,0,0,0,0};

#pragma unroll
    for (int l = 0; l < 8; l++) {
        float col[8], y[8];
#pragma unroll
        for (int i = 0; i < 8; i++) col[i] = T[i][l];
        dct8(col, y);
#pragma unroll
        for (int k = 0; k < 8; k++) {
            float a = fabsf(y[k]);
            int band = BAND_OF[k * 8 + l];   // compile-time constant
            bs[band] += a;
            bq[band] = fmaf(a, a, bq[band]);
        }
    }

    // warp tree-reduce the 16 accumulators
#pragma unroll
    for (int m = 0; m < 8; m++) {
#pragma unroll
        for (int off = 16; off > 0; off >>= 1) {
            bs[m] += __shfl_down_sync(0xFFFFFFFFu, bs[m], off);
            bq[m] += __shfl_down_sync(0xFFFFFFFFu, bq[m], off);
        }
    }

    __shared__ float red[4][16];
    int wid = tid >> 5, lane = tid & 31;
    if (lane == 0) {
#pragma unroll
        for (int m = 0; m < 8; m++) {
            red[wid][m]     = bs[m];
            red[wid][8 + m] = bq[m];
        }
    }
    __syncthreads();
    if (tid < 16) {
        float v = red[0][tid] + red[1][tid] + red[2][tid] + red[3][tid];
        g_part[g * 16 + tid] = v;
    }
}

__global__ void __launch_bounds__(256)
finalize_kernel(const float* __restrict__ W, const float* __restrict__ bias,
                float* __restrict__ out)
{
    __shared__ float sh[8][16];
    __shared__ float tot[16];
    __shared__ float raw[16];

    int b = blockIdx.x;       // image
    int t = threadIdx.x;
    int s   = t & 15;         // accumulator slot
    int grp = t >> 4;         // 16 groups x 8 strips each

    // coalesced: consecutive t -> contiguous 64B
    const float* p = g_part + (size_t)b * NB * 16 + grp * 8 * 16 + s;
    float acc = 0.0f;
#pragma unroll
    for (int c = 0; c < 8; c++) acc += p[c * 16];

    // fold group pairs within each warp (lanes 0-15 <- +lanes 16-31)
    acc += __shfl_down_sync(0xFFFFFFFFu, acc, 16);
    if ((t & 31) < 16) sh[t >> 5][s] = acc;
    __syncthreads();

    if (t < 16) {
        float v = 0.0f;
#pragma unroll
        for (int w = 0; w < 8; w++) v += sh[w][t];
        tot[t] = v;
    }
    __syncthreads();

    if (t < 8) {
        double sum = (double)tot[t];
        double sq  = (double)tot[t + 8];
        double mean = sum / NVALS;
        double var  = (sq - NVALS * mean * mean) / (NVALS - 1.0);
        if (var < 0.0) var = 0.0;
        raw[t]     = (float)mean;
        raw[t + 8] = (float)sqrt(var);
    }
    __syncthreads();

    for (int f = t; f < 512; f += 256) {
        float acc2 = bias[f];
#pragma unroll
        for (int j = 0; j < 16; j++)
            acc2 = fmaf(raw[j], W[f * 16 + j], acc2);
        out[b * 512 + f] = acc2;
    }
}

extern "C" void kernel_launch(void* const* d_in, const int* in_sizes, int n_in,
                              void* d_out, int out_size)
{
    const float* img  = (const float*)d_in[0];   // [32,3,1024,1024] f32
    // d_in[1] (dct_matrix) baked in as immediates; d_in[2] (zigzag) baked into BAND_OF
    const float* W    = (const float*)d_in[3];   // [512,16] f32
    const float* bias = (const float*)d_in[4];   // [512] f32
    float* out = (float*)d_out;                  // [32,512] f32

    dct_stats_kernel<<<NCTA, 128>>>(img);
    finalize_kernel<<<NIMG, 256>>>(W, bias, out);
}